// round 15
// baseline (speedup 1.0000x reference)
#include <cuda_runtime.h>
#include <math.h>

#define Bb   2
#define Ss   2048
#define Dd   1024
#define Hh   16
#define DKk  64
#define Mtot (Bb*Ss)   // 4096

// ---------------- scratch (static device memory; no allocations) -------------
__device__ float g_Q [Bb*Hh*Ss*DKk];   // [B,H,S,DK]
__device__ float g_K [Bb*Hh*Ss*DKk];
__device__ float g_V [Bb*Hh*Ss*DKk];
__device__ float g_Ks[Bb*Hh*Ss*DKk];   // smeared K + PE
__device__ float g_attn[Bb*Ss*Dd];     // [B,S,D]
__device__ float g_Y [Bb*Ss*Dd];       // pre-LN output

// ---------------- QKV projection GEMM ----------------------------------------
// C[m][n] = sum_k X[m][k] * W[n][k]   (torch Linear: x @ W.T)
// Output written directly in [B,H,S,DK] layout. blockIdx.z selects Q/K/V.
// Tiles: BM=64, BN=64, BK=16, 256 threads, 4x4 per thread.
__global__ void __launch_bounds__(256) qkv_gemm(const float* __restrict__ X,
                                                const float* __restrict__ Wq,
                                                const float* __restrict__ Wk,
                                                const float* __restrict__ Wv)
{
    __shared__ float sA[64*16];
    __shared__ float sB[16*64];   // transposed: sB[k][n]

    const float* W  = (blockIdx.z == 0) ? Wq : (blockIdx.z == 1) ? Wk : Wv;
    float*       out= (blockIdx.z == 0) ? g_Q : (blockIdx.z == 1) ? g_K : g_V;

    const int tid = threadIdx.x;
    const int tx  = tid & 15;
    const int ty  = tid >> 4;
    const int m0  = blockIdx.y * 64;
    const int n0  = blockIdx.x * 64;

    float acc[4][4] = {};

    const int lr = tid >> 2;          // 0..63
    const int lc = (tid & 3) * 4;     // 0,4,8,12

    for (int k0 = 0; k0 < Dd; k0 += 16) {
        float4 av = *(const float4*)&X[(size_t)(m0 + lr) * Dd + k0 + lc];
        *(float4*)&sA[lr * 16 + lc] = av;
        float4 wv = *(const float4*)&W[(size_t)(n0 + lr) * Dd + k0 + lc];
        sB[(lc + 0) * 64 + lr] = wv.x;
        sB[(lc + 1) * 64 + lr] = wv.y;
        sB[(lc + 2) * 64 + lr] = wv.z;
        sB[(lc + 3) * 64 + lr] = wv.w;
        __syncthreads();

        #pragma unroll
        for (int k = 0; k < 16; k++) {
            float4 bv = *(float4*)&sB[k * 64 + tx * 4];
            #pragma unroll
            for (int i = 0; i < 4; i++) {
                float a = sA[(ty * 4 + i) * 16 + k];
                acc[i][0] += a * bv.x;
                acc[i][1] += a * bv.y;
                acc[i][2] += a * bv.z;
                acc[i][3] += a * bv.w;
            }
        }
        __syncthreads();
    }

    const int h = blockIdx.x;  // BN == DK, so each x-block is one head
    #pragma unroll
    for (int i = 0; i < 4; i++) {
        int m = m0 + ty * 4 + i;
        int b = m >> 11;           // /S
        int s = m & 2047;          // %S
        float4 o = make_float4(acc[i][0], acc[i][1], acc[i][2], acc[i][3]);
        *(float4*)&out[(((size_t)(b * Hh + h) * Ss + s) * DKk) + tx * 4] = o;
    }
}

// ---------------- EMA smear + sinusoidal PE -----------------------------------
// Ks[b,h,0]   = K[b,h,0] + pe[0]
// Ks[b,h,s]   = a*K[s] + (1-a)*K[s-1] + pe[s],  a = sigmoid(alpha[h,s-1])
// Q[b,h,s]   += pe[s]
__global__ void smear_pe(const float* __restrict__ alpha)
{
    int idx = blockIdx.x * blockDim.x + threadIdx.x;   // over B*H*S*DK
    int dk = idx & 63;
    int s  = (idx >> 6)  & 2047;
    int h  = (idx >> 17) & 15;

    int   i    = dk >> 1;
    float freq = expf(-(2.0f * (float)i / 64.0f) * logf(10000.0f));
    float ang  = (float)s * freq;
    float pe   = (dk & 1) ? cosf(ang) : sinf(ang);

    float kv = g_K[idx];
    float ks;
    if (s == 0) {
        ks = kv;
    } else {
        float a = 1.0f / (1.0f + expf(-alpha[h * (Ss - 1) + (s - 1)]));
        ks = a * kv + (1.0f - a) * g_K[idx - DKk];
    }
    g_Ks[idx] = ks + pe;
    g_Q[idx] += pe;
}

// ---------------- flash attention (causal, fp32) ------------------------------
// Block: 64 queries of one (b,h); 256 threads as 16x16, 4x4 micro-tiles.
// SMEM: sQ[64x64] + sKP[64x64] (K^T, then reused for P) + sV[64x64] = 48 KB.
__global__ void __launch_bounds__(256) flash_attn()
{
    __shared__ float sQ [64 * 64];
    __shared__ float sKP[64 * 64];
    __shared__ float sV [64 * 64];

    const int bh = blockIdx.y;          // 0..31  (b*H + h)
    const int qt = blockIdx.x;          // query tile
    const int tid = threadIdx.x;
    const int tx = tid & 15;
    const int ty = tid >> 4;

    const float* Qp = &g_Q [(size_t)bh * Ss * DKk];
    const float* Kp = &g_Ks[(size_t)bh * Ss * DKk];
    const float* Vp = &g_V [(size_t)bh * Ss * DKk];

    const int lr = tid >> 2;            // 0..63
    const int lc0 = (tid & 3) * 16;     // 0,16,32,48

    // load Q tile: 4 float4 per thread
    #pragma unroll
    for (int u = 0; u < 4; u++) {
        float4 v = *(const float4*)&Qp[(size_t)(qt * 64 + lr) * DKk + lc0 + u * 4];
        *(float4*)&sQ[lr * 64 + lc0 + u * 4] = v;
    }

    float m_i[4], l_i[4], acc[4][4];
    #pragma unroll
    for (int i = 0; i < 4; i++) {
        m_i[i] = -INFINITY;
        l_i[i] = 0.0f;
        #pragma unroll
        for (int j = 0; j < 4; j++) acc[i][j] = 0.0f;
    }

    for (int kt = 0; kt <= qt; kt++) {
        // load K (transposed) and V tiles
        #pragma unroll
        for (int u = 0; u < 4; u++) {
            float4 kv = *(const float4*)&Kp[(size_t)(kt * 64 + lr) * DKk + lc0 + u * 4];
            sKP[(lc0 + u * 4 + 0) * 64 + lr] = kv.x;
            sKP[(lc0 + u * 4 + 1) * 64 + lr] = kv.y;
            sKP[(lc0 + u * 4 + 2) * 64 + lr] = kv.z;
            sKP[(lc0 + u * 4 + 3) * 64 + lr] = kv.w;
            float4 vv = *(const float4*)&Vp[(size_t)(kt * 64 + lr) * DKk + lc0 + u * 4];
            *(float4*)&sV[lr * 64 + lc0 + u * 4] = vv;
        }
        __syncthreads();

        // scores = Q @ K^T
        float sc[4][4] = {};
        #pragma unroll 8
        for (int kd = 0; kd < 64; kd++) {
            float4 kvec = *(float4*)&sKP[kd * 64 + tx * 4];
            #pragma unroll
            for (int i = 0; i < 4; i++) {
                float q = sQ[(ty * 4 + i) * 64 + kd];
                sc[i][0] += q * kvec.x;
                sc[i][1] += q * kvec.y;
                sc[i][2] += q * kvec.z;
                sc[i][3] += q * kvec.w;
            }
        }
        __syncthreads();   // done reading sKP; safe to overwrite with P

        // scale + causal mask (diagonal tile only)
        #pragma unroll
        for (int i = 0; i < 4; i++)
            #pragma unroll
            for (int j = 0; j < 4; j++) {
                sc[i][j] *= 0.125f;   // 1/sqrt(64)
                if (kt == qt && (tx * 4 + j) > (ty * 4 + i)) sc[i][j] = -INFINITY;
            }

        // online softmax (per row; 16 threads per row group, half-warp aligned)
        #pragma unroll
        for (int i = 0; i < 4; i++) {
            float mx = fmaxf(fmaxf(sc[i][0], sc[i][1]), fmaxf(sc[i][2], sc[i][3]));
            #pragma unroll
            for (int m = 8; m >= 1; m >>= 1)
                mx = fmaxf(mx, __shfl_xor_sync(0xffffffffu, mx, m));
            float m_new = fmaxf(m_i[i], mx);
            float p0 = expf(sc[i][0] - m_new);
            float p1 = expf(sc[i][1] - m_new);
            float p2 = expf(sc[i][2] - m_new);
            float p3 = expf(sc[i][3] - m_new);
            float rs = p0 + p1 + p2 + p3;
            #pragma unroll
            for (int m = 8; m >= 1; m >>= 1)
                rs += __shfl_xor_sync(0xffffffffu, rs, m);
            float corr = expf(m_i[i] - m_new);
            l_i[i] = l_i[i] * corr + rs;
            m_i[i] = m_new;
            #pragma unroll
            for (int j = 0; j < 4; j++) acc[i][j] *= corr;
            // stash probabilities into the K buffer
            sKP[(ty * 4 + i) * 64 + tx * 4 + 0] = p0;
            sKP[(ty * 4 + i) * 64 + tx * 4 + 1] = p1;
            sKP[(ty * 4 + i) * 64 + tx * 4 + 2] = p2;
            sKP[(ty * 4 + i) * 64 + tx * 4 + 3] = p3;
        }
        __syncthreads();

        // O += P @ V
        #pragma unroll 8
        for (int kk = 0; kk < 64; kk++) {
            float4 vv = *(float4*)&sV[kk * 64 + tx * 4];
            #pragma unroll
            for (int i = 0; i < 4; i++) {
                float p = sKP[(ty * 4 + i) * 64 + kk];
                acc[i][0] += p * vv.x;
                acc[i][1] += p * vv.y;
                acc[i][2] += p * vv.z;
                acc[i][3] += p * vv.w;
            }
        }
        __syncthreads();   // before next tile overwrites sKP/sV
    }

    // epilogue: write attn in [B,S,D]
    const int b = bh >> 4;
    const int h = bh & 15;
    #pragma unroll
    for (int i = 0; i < 4; i++) {
        int q = qt * 64 + ty * 4 + i;
        float inv = 1.0f / l_i[i];
        float4 o = make_float4(acc[i][0] * inv, acc[i][1] * inv,
                               acc[i][2] * inv, acc[i][3] * inv);
        *(float4*)&g_attn[((size_t)(b * Ss + q)) * Dd + h * DKk + tx * 4] = o;
    }
}

// ---------------- output projection + residual --------------------------------
__global__ void __launch_bounds__(256) o_gemm(const float* __restrict__ X,
                                              const float* __restrict__ Wo)
{
    __shared__ float sA[64*16];
    __shared__ float sB[16*64];

    const int tid = threadIdx.x;
    const int tx  = tid & 15;
    const int ty  = tid >> 4;
    const int m0  = blockIdx.y * 64;
    const int n0  = blockIdx.x * 64;

    float acc[4][4] = {};
    const int lr = tid >> 2;
    const int lc = (tid & 3) * 4;

    for (int k0 = 0; k0 < Dd; k0 += 16) {
        float4 av = *(const float4*)&g_attn[(size_t)(m0 + lr) * Dd + k0 + lc];
        *(float4*)&sA[lr * 16 + lc] = av;
        float4 wv = *(const float4*)&Wo[(size_t)(n0 + lr) * Dd + k0 + lc];
        sB[(lc + 0) * 64 + lr] = wv.x;
        sB[(lc + 1) * 64 + lr] = wv.y;
        sB[(lc + 2) * 64 + lr] = wv.z;
        sB[(lc + 3) * 64 + lr] = wv.w;
        __syncthreads();

        #pragma unroll
        for (int k = 0; k < 16; k++) {
            float4 bv = *(float4*)&sB[k * 64 + tx * 4];
            #pragma unroll
            for (int i = 0; i < 4; i++) {
                float a = sA[(ty * 4 + i) * 16 + k];
                acc[i][0] += a * bv.x;
                acc[i][1] += a * bv.y;
                acc[i][2] += a * bv.z;
                acc[i][3] += a * bv.w;
            }
        }
        __syncthreads();
    }

    #pragma unroll
    for (int i = 0; i < 4; i++) {
        int m = m0 + ty * 4 + i;
        float4 xr = *(const float4*)&X[(size_t)m * Dd + n0 + tx * 4];
        float4 o = make_float4(acc[i][0] + xr.x, acc[i][1] + xr.y,
                               acc[i][2] + xr.z, acc[i][3] + xr.w);
        *(float4*)&g_Y[(size_t)m * Dd + n0 + tx * 4] = o;
    }
}

// ---------------- LayerNorm ----------------------------------------------------
__global__ void __launch_bounds__(256) layernorm(const float* __restrict__ scale,
                                                 const float* __restrict__ bias,
                                                 float* __restrict__ out)
{
    const int row = blockIdx.x;
    const float* y = &g_Y[(size_t)row * Dd];
    const int tid = threadIdx.x;

    float4 v = *(const float4*)&y[tid * 4];
    float s  = v.x + v.y + v.z + v.w;
    float ss = v.x*v.x + v.y*v.y + v.z*v.z + v.w*v.w;

    #pragma unroll
    for (int m = 16; m >= 1; m >>= 1) {
        s  += __shfl_xor_sync(0xffffffffu, s,  m);
        ss += __shfl_xor_sync(0xffffffffu, ss, m);
    }
    __shared__ float red_s[8], red_ss[8];
    int wid = tid >> 5, lane = tid & 31;
    if (lane == 0) { red_s[wid] = s; red_ss[wid] = ss; }
    __syncthreads();
    s = 0.0f; ss = 0.0f;
    #pragma unroll
    for (int w = 0; w < 8; w++) { s += red_s[w]; ss += red_ss[w]; }

    float mu  = s * (1.0f / Dd);
    float var = ss * (1.0f / Dd) - mu * mu;
    float inv = rsqrtf(var + 1e-5f);

    float4 sc = *(const float4*)&scale[tid * 4];
    float4 bi = *(const float4*)&bias[tid * 4];
    float4 o;
    o.x = (v.x - mu) * inv * sc.x + bi.x;
    o.y = (v.y - mu) * inv * sc.y + bi.y;
    o.z = (v.z - mu) * inv * sc.z + bi.z;
    o.w = (v.w - mu) * inv * sc.w + bi.w;
    *(float4*)&out[(size_t)row * Dd + tid * 4] = o;
}

// ---------------- launch --------------------------------------------------------
extern "C" void kernel_launch(void* const* d_in, const int* in_sizes, int n_in,
                              void* d_out, int out_size)
{
    const float* X        = (const float*)d_in[0];
    const float* W_q      = (const float*)d_in[1];
    const float* W_k      = (const float*)d_in[2];
    const float* W_v      = (const float*)d_in[3];
    const float* W_o      = (const float*)d_in[4];
    const float* alpha    = (const float*)d_in[5];
    const float* ln_scale = (const float*)d_in[6];
    const float* ln_bias  = (const float*)d_in[7];
    float* out = (float*)d_out;

    // 1) Q/K/V projections
    dim3 gq(Dd / 64, Mtot / 64, 3);
    qkv_gemm<<<gq, 256>>>(X, W_q, W_k, W_v);

    // 2) EMA smear + PE
    smear_pe<<<(Bb * Hh * Ss * DKk) / 256, 256>>>(alpha);

    // 3) causal flash attention
    dim3 ga(Ss / 64, Bb * Hh);
    flash_attn<<<ga, 256>>>();

    // 4) output projection + residual
    dim3 go(Dd / 64, Mtot / 64);
    o_gemm<<<go, 256>>>(X, W_o);

    // 5) LayerNorm -> d_out
    layernorm<<<Mtot, 256>>>(ln_scale, ln_bias, out);
}

// round 16
// speedup vs baseline: 1.0769x; 1.0769x over previous
#include <cuda_runtime.h>
#include <math.h>

#define Bb   2
#define Ss   2048
#define Dd   1024
#define Hh   16
#define DKk  64
#define Mtot (Bb*Ss)   // 4096

// ---------------- scratch (static device memory; no allocations) -------------
__device__ float g_Q [Bb*Hh*Ss*DKk];   // [B,H,S,DK]
__device__ float g_K [Bb*Hh*Ss*DKk];
__device__ float g_V [Bb*Hh*Ss*DKk];
__device__ float g_Ks[Bb*Hh*Ss*DKk];   // smeared K + PE
__device__ float g_attn[Bb*Ss*Dd];     // [B,S,D]
__device__ float g_Y [Bb*Ss*Dd];       // pre-LN output

#define ASTR 136
#define BSTR 68

// ---------------- QKV projection GEMM (high-intensity, 8x4 microtile) ---------
// C[m][n] = sum_k X[m][k] * W[n][k]   (torch Linear: x @ W.T)
// BM=128, BN=64, BK=16; 256 threads as (tx 0..15 -> 4 cols, ty 0..15 -> 8 rows).
// sAT: A transposed [k][m] stride 136 (broadcast reads); sB: W^T [k][n] stride 68.
// Output written directly in [B,H,S,DK] layout; blockIdx.z selects Q/K/V.
__global__ void __launch_bounds__(256) qkv_gemm_b(const float* __restrict__ X,
                                                  const float* __restrict__ Wq,
                                                  const float* __restrict__ Wk,
                                                  const float* __restrict__ Wv)
{
    __shared__ float sAT[16 * ASTR];
    __shared__ float sB [16 * BSTR];

    const float* W  = (blockIdx.z == 0) ? Wq : (blockIdx.z == 1) ? Wk : Wv;
    float*      out = (blockIdx.z == 0) ? g_Q : (blockIdx.z == 1) ? g_K : g_V;

    const int tid = threadIdx.x;
    const int tx  = tid & 15;          // n micro (4 cols)
    const int ty  = tid >> 4;          // m micro (8 rows)
    const int m0  = blockIdx.y * 128;
    const int n0  = blockIdx.x * 64;

    float acc[8][4] = {};

    const int lr = tid >> 2;           // 0..63
    const int lc = (tid & 3) * 4;      // 0,4,8,12

    for (int k0 = 0; k0 < Dd; k0 += 16) {
        // A tile -> sAT[k][m], two row passes of 64
        #pragma unroll
        for (int p = 0; p < 2; p++) {
            int row = lr + p * 64;
            float4 av = *(const float4*)&X[(size_t)(m0 + row) * Dd + k0 + lc];
            sAT[(lc + 0) * ASTR + row] = av.x;
            sAT[(lc + 1) * ASTR + row] = av.y;
            sAT[(lc + 2) * ASTR + row] = av.z;
            sAT[(lc + 3) * ASTR + row] = av.w;
        }
        // W tile -> sB[k][n]
        {
            float4 wv = *(const float4*)&W[(size_t)(n0 + lr) * Dd + k0 + lc];
            sB[(lc + 0) * BSTR + lr] = wv.x;
            sB[(lc + 1) * BSTR + lr] = wv.y;
            sB[(lc + 2) * BSTR + lr] = wv.z;
            sB[(lc + 3) * BSTR + lr] = wv.w;
        }
        __syncthreads();

        #pragma unroll
        for (int k = 0; k < 16; k++) {
            float4 a0 = *(float4*)&sAT[k * ASTR + ty * 8];
            float4 a1 = *(float4*)&sAT[k * ASTR + ty * 8 + 4];
            float4 b  = *(float4*)&sB [k * BSTR + tx * 4];
            acc[0][0] += a0.x * b.x; acc[0][1] += a0.x * b.y; acc[0][2] += a0.x * b.z; acc[0][3] += a0.x * b.w;
            acc[1][0] += a0.y * b.x; acc[1][1] += a0.y * b.y; acc[1][2] += a0.y * b.z; acc[1][3] += a0.y * b.w;
            acc[2][0] += a0.z * b.x; acc[2][1] += a0.z * b.y; acc[2][2] += a0.z * b.z; acc[2][3] += a0.z * b.w;
            acc[3][0] += a0.w * b.x; acc[3][1] += a0.w * b.y; acc[3][2] += a0.w * b.z; acc[3][3] += a0.w * b.w;
            acc[4][0] += a1.x * b.x; acc[4][1] += a1.x * b.y; acc[4][2] += a1.x * b.z; acc[4][3] += a1.x * b.w;
            acc[5][0] += a1.y * b.x; acc[5][1] += a1.y * b.y; acc[5][2] += a1.y * b.z; acc[5][3] += a1.y * b.w;
            acc[6][0] += a1.z * b.x; acc[6][1] += a1.z * b.y; acc[6][2] += a1.z * b.z; acc[6][3] += a1.z * b.w;
            acc[7][0] += a1.w * b.x; acc[7][1] += a1.w * b.y; acc[7][2] += a1.w * b.z; acc[7][3] += a1.w * b.w;
        }
        __syncthreads();
    }

    const int h = blockIdx.x;          // BN == DK, one head per x-block
    #pragma unroll
    for (int i = 0; i < 8; i++) {
        int m = m0 + ty * 8 + i;
        int b = m >> 11;               // /S
        int s = m & 2047;              // %S
        *(float4*)&out[(((size_t)(b * Hh + h) * Ss + s) * DKk) + tx * 4] =
            make_float4(acc[i][0], acc[i][1], acc[i][2], acc[i][3]);
    }
}

// ---------------- output projection + residual (same tiling) -------------------
__global__ void __launch_bounds__(256) o_gemm_b(const float* __restrict__ X,
                                                const float* __restrict__ Wo)
{
    __shared__ float sAT[16 * ASTR];
    __shared__ float sB [16 * BSTR];

    const int tid = threadIdx.x;
    const int tx  = tid & 15;
    const int ty  = tid >> 4;
    const int m0  = blockIdx.y * 128;
    const int n0  = blockIdx.x * 64;

    float acc[8][4] = {};

    const int lr = tid >> 2;
    const int lc = (tid & 3) * 4;

    for (int k0 = 0; k0 < Dd; k0 += 16) {
        #pragma unroll
        for (int p = 0; p < 2; p++) {
            int row = lr + p * 64;
            float4 av = *(const float4*)&g_attn[(size_t)(m0 + row) * Dd + k0 + lc];
            sAT[(lc + 0) * ASTR + row] = av.x;
            sAT[(lc + 1) * ASTR + row] = av.y;
            sAT[(lc + 2) * ASTR + row] = av.z;
            sAT[(lc + 3) * ASTR + row] = av.w;
        }
        {
            float4 wv = *(const float4*)&Wo[(size_t)(n0 + lr) * Dd + k0 + lc];
            sB[(lc + 0) * BSTR + lr] = wv.x;
            sB[(lc + 1) * BSTR + lr] = wv.y;
            sB[(lc + 2) * BSTR + lr] = wv.z;
            sB[(lc + 3) * BSTR + lr] = wv.w;
        }
        __syncthreads();

        #pragma unroll
        for (int k = 0; k < 16; k++) {
            float4 a0 = *(float4*)&sAT[k * ASTR + ty * 8];
            float4 a1 = *(float4*)&sAT[k * ASTR + ty * 8 + 4];
            float4 b  = *(float4*)&sB [k * BSTR + tx * 4];
            acc[0][0] += a0.x * b.x; acc[0][1] += a0.x * b.y; acc[0][2] += a0.x * b.z; acc[0][3] += a0.x * b.w;
            acc[1][0] += a0.y * b.x; acc[1][1] += a0.y * b.y; acc[1][2] += a0.y * b.z; acc[1][3] += a0.y * b.w;
            acc[2][0] += a0.z * b.x; acc[2][1] += a0.z * b.y; acc[2][2] += a0.z * b.z; acc[2][3] += a0.z * b.w;
            acc[3][0] += a0.w * b.x; acc[3][1] += a0.w * b.y; acc[3][2] += a0.w * b.z; acc[3][3] += a0.w * b.w;
            acc[4][0] += a1.x * b.x; acc[4][1] += a1.x * b.y; acc[4][2] += a1.x * b.z; acc[4][3] += a1.x * b.w;
            acc[5][0] += a1.y * b.x; acc[5][1] += a1.y * b.y; acc[5][2] += a1.y * b.z; acc[5][3] += a1.y * b.w;
            acc[6][0] += a1.z * b.x; acc[6][1] += a1.z * b.y; acc[6][2] += a1.z * b.z; acc[6][3] += a1.z * b.w;
            acc[7][0] += a1.w * b.x; acc[7][1] += a1.w * b.y; acc[7][2] += a1.w * b.z; acc[7][3] += a1.w * b.w;
        }
        __syncthreads();
    }

    #pragma unroll
    for (int i = 0; i < 8; i++) {
        int m = m0 + ty * 8 + i;
        float4 xr = *(const float4*)&X[(size_t)m * Dd + n0 + tx * 4];
        *(float4*)&g_Y[(size_t)m * Dd + n0 + tx * 4] =
            make_float4(acc[i][0] + xr.x, acc[i][1] + xr.y,
                        acc[i][2] + xr.z, acc[i][3] + xr.w);
    }
}

// ---------------- EMA smear + sinusoidal PE (byte-identical to round 15) -------
__global__ void smear_pe(const float* __restrict__ alpha)
{
    int idx = blockIdx.x * blockDim.x + threadIdx.x;   // over B*H*S*DK
    int dk = idx & 63;
    int s  = (idx >> 6)  & 2047;
    int h  = (idx >> 17) & 15;

    int   i    = dk >> 1;
    float freq = expf(-(2.0f * (float)i / 64.0f) * logf(10000.0f));
    float ang  = (float)s * freq;
    float pe   = (dk & 1) ? cosf(ang) : sinf(ang);

    float kv = g_K[idx];
    float ks;
    if (s == 0) {
        ks = kv;
    } else {
        float a = 1.0f / (1.0f + expf(-alpha[h * (Ss - 1) + (s - 1)]));
        ks = a * kv + (1.0f - a) * g_K[idx - DKk];
    }
    g_Ks[idx] = ks + pe;
    g_Q[idx] += pe;
}

// ---------------- flash attention (byte-identical to round 15) -----------------
__global__ void __launch_bounds__(256) flash_attn()
{
    __shared__ float sQ [64 * 64];
    __shared__ float sKP[64 * 64];
    __shared__ float sV [64 * 64];

    const int bh = blockIdx.y;          // 0..31  (b*H + h)
    const int qt = blockIdx.x;          // query tile
    const int tid = threadIdx.x;
    const int tx = tid & 15;
    const int ty = tid >> 4;

    const float* Qp = &g_Q [(size_t)bh * Ss * DKk];
    const float* Kp = &g_Ks[(size_t)bh * Ss * DKk];
    const float* Vp = &g_V [(size_t)bh * Ss * DKk];

    const int lr = tid >> 2;            // 0..63
    const int lc0 = (tid & 3) * 16;     // 0,16,32,48

    #pragma unroll
    for (int u = 0; u < 4; u++) {
        float4 v = *(const float4*)&Qp[(size_t)(qt * 64 + lr) * DKk + lc0 + u * 4];
        *(float4*)&sQ[lr * 64 + lc0 + u * 4] = v;
    }

    float m_i[4], l_i[4], acc[4][4];
    #pragma unroll
    for (int i = 0; i < 4; i++) {
        m_i[i] = -INFINITY;
        l_i[i] = 0.0f;
        #pragma unroll
        for (int j = 0; j < 4; j++) acc[i][j] = 0.0f;
    }

    for (int kt = 0; kt <= qt; kt++) {
        #pragma unroll
        for (int u = 0; u < 4; u++) {
            float4 kv = *(const float4*)&Kp[(size_t)(kt * 64 + lr) * DKk + lc0 + u * 4];
            sKP[(lc0 + u * 4 + 0) * 64 + lr] = kv.x;
            sKP[(lc0 + u * 4 + 1) * 64 + lr] = kv.y;
            sKP[(lc0 + u * 4 + 2) * 64 + lr] = kv.z;
            sKP[(lc0 + u * 4 + 3) * 64 + lr] = kv.w;
            float4 vv = *(const float4*)&Vp[(size_t)(kt * 64 + lr) * DKk + lc0 + u * 4];
            *(float4*)&sV[lr * 64 + lc0 + u * 4] = vv;
        }
        __syncthreads();

        float sc[4][4] = {};
        #pragma unroll 8
        for (int kd = 0; kd < 64; kd++) {
            float4 kvec = *(float4*)&sKP[kd * 64 + tx * 4];
            #pragma unroll
            for (int i = 0; i < 4; i++) {
                float q = sQ[(ty * 4 + i) * 64 + kd];
                sc[i][0] += q * kvec.x;
                sc[i][1] += q * kvec.y;
                sc[i][2] += q * kvec.z;
                sc[i][3] += q * kvec.w;
            }
        }
        __syncthreads();

        #pragma unroll
        for (int i = 0; i < 4; i++)
            #pragma unroll
            for (int j = 0; j < 4; j++) {
                sc[i][j] *= 0.125f;   // 1/sqrt(64)
                if (kt == qt && (tx * 4 + j) > (ty * 4 + i)) sc[i][j] = -INFINITY;
            }

        #pragma unroll
        for (int i = 0; i < 4; i++) {
            float mx = fmaxf(fmaxf(sc[i][0], sc[i][1]), fmaxf(sc[i][2], sc[i][3]));
            #pragma unroll
            for (int m = 8; m >= 1; m >>= 1)
                mx = fmaxf(mx, __shfl_xor_sync(0xffffffffu, mx, m));
            float m_new = fmaxf(m_i[i], mx);
            float p0 = expf(sc[i][0] - m_new);
            float p1 = expf(sc[i][1] - m_new);
            float p2 = expf(sc[i][2] - m_new);
            float p3 = expf(sc[i][3] - m_new);
            float rs = p0 + p1 + p2 + p3;
            #pragma unroll
            for (int m = 8; m >= 1; m >>= 1)
                rs += __shfl_xor_sync(0xffffffffu, rs, m);
            float corr = expf(m_i[i] - m_new);
            l_i[i] = l_i[i] * corr + rs;
            m_i[i] = m_new;
            #pragma unroll
            for (int j = 0; j < 4; j++) acc[i][j] *= corr;
            sKP[(ty * 4 + i) * 64 + tx * 4 + 0] = p0;
            sKP[(ty * 4 + i) * 64 + tx * 4 + 1] = p1;
            sKP[(ty * 4 + i) * 64 + tx * 4 + 2] = p2;
            sKP[(ty * 4 + i) * 64 + tx * 4 + 3] = p3;
        }
        __syncthreads();

        #pragma unroll 8
        for (int kk = 0; kk < 64; kk++) {
            float4 vv = *(float4*)&sV[kk * 64 + tx * 4];
            #pragma unroll
            for (int i = 0; i < 4; i++) {
                float p = sKP[(ty * 4 + i) * 64 + kk];
                acc[i][0] += p * vv.x;
                acc[i][1] += p * vv.y;
                acc[i][2] += p * vv.z;
                acc[i][3] += p * vv.w;
            }
        }
        __syncthreads();
    }

    const int b = bh >> 4;
    const int h = bh & 15;
    #pragma unroll
    for (int i = 0; i < 4; i++) {
        int q = qt * 64 + ty * 4 + i;
        float inv = 1.0f / l_i[i];
        float4 o = make_float4(acc[i][0] * inv, acc[i][1] * inv,
                               acc[i][2] * inv, acc[i][3] * inv);
        *(float4*)&g_attn[((size_t)(b * Ss + q)) * Dd + h * DKk + tx * 4] = o;
    }
}

// ---------------- LayerNorm (byte-identical to round 15) -----------------------
__global__ void __launch_bounds__(256) layernorm(const float* __restrict__ scale,
                                                 const float* __restrict__ bias,
                                                 float* __restrict__ out)
{
    const int row = blockIdx.x;
    const float* y = &g_Y[(size_t)row * Dd];
    const int tid = threadIdx.x;

    float4 v = *(const float4*)&y[tid * 4];
    float s  = v.x + v.y + v.z + v.w;
    float ss = v.x*v.x + v.y*v.y + v.z*v.z + v.w*v.w;

    #pragma unroll
    for (int m = 16; m >= 1; m >>= 1) {
        s  += __shfl_xor_sync(0xffffffffu, s,  m);
        ss += __shfl_xor_sync(0xffffffffu, ss, m);
    }
    __shared__ float red_s[8], red_ss[8];
    int wid = tid >> 5, lane = tid & 31;
    if (lane == 0) { red_s[wid] = s; red_ss[wid] = ss; }
    __syncthreads();
    s = 0.0f; ss = 0.0f;
    #pragma unroll
    for (int w = 0; w < 8; w++) { s += red_s[w]; ss += red_ss[w]; }

    float mu  = s * (1.0f / Dd);
    float var = ss * (1.0f / Dd) - mu * mu;
    float inv = rsqrtf(var + 1e-5f);

    float4 sc = *(const float4*)&scale[tid * 4];
    float4 bi = *(const float4*)&bias[tid * 4];
    float4 o;
    o.x = (v.x - mu) * inv * sc.x + bi.x;
    o.y = (v.y - mu) * inv * sc.y + bi.y;
    o.z = (v.z - mu) * inv * sc.z + bi.z;
    o.w = (v.w - mu) * inv * sc.w + bi.w;
    *(float4*)&out[(size_t)row * Dd + tid * 4] = o;
}

// ---------------- launch --------------------------------------------------------
extern "C" void kernel_launch(void* const* d_in, const int* in_sizes, int n_in,
                              void* d_out, int out_size)
{
    const float* X        = (const float*)d_in[0];
    const float* W_q      = (const float*)d_in[1];
    const float* W_k      = (const float*)d_in[2];
    const float* W_v      = (const float*)d_in[3];
    const float* W_o      = (const float*)d_in[4];
    const float* alpha    = (const float*)d_in[5];
    const float* ln_scale = (const float*)d_in[6];
    const float* ln_bias  = (const float*)d_in[7];
    float* out = (float*)d_out;

    // 1) Q/K/V projections (high-intensity FFMA, BM=128)
    dim3 gq(Dd / 64, Mtot / 128, 3);
    qkv_gemm_b<<<gq, 256>>>(X, W_q, W_k, W_v);

    // 2) EMA smear + PE
    smear_pe<<<(Bb * Hh * Ss * DKk) / 256, 256>>>(alpha);

    // 3) causal flash attention
    dim3 ga(Ss / 64, Bb * Hh);
    flash_attn<<<ga, 256>>>();

    // 4) output projection + residual (high-intensity FFMA, BM=128)
    dim3 go(Dd / 64, Mtot / 128);
    o_gemm_b<<<go, 256>>>(X, W_o);

    // 5) LayerNorm -> d_out
    layernorm<<<Mtot, 256>>>(ln_scale, ln_bias, out);
}